// round 11
// baseline (speedup 1.0000x reference)
#include <cuda_runtime.h>
#include <cstdint>

#define BATCH  64
#define HID    1024
#define VOCAB  4096
#define SEQ    256
#define NBLK   128
#define NTHR   512
#define CH     128                 // A-chunk width (cols of K)
#define NCH    (HID / CH)          // 8 chunks
#define SAPAD  132                 // padded row stride for sA
#define NSTG   3                   // cp.async pipeline stages

// ---------------------------------------------------------------------------
// Global scratch
// ---------------------------------------------------------------------------
__device__ float g_H[(SEQ + 1) * BATCH * HID];
__device__ float g_P[BATCH * HID];
__device__ unsigned g_bar_count = 0;
__device__ unsigned g_bar_gen   = 0;
__device__ unsigned g_cntA[8];     // per K-group: blocks done with phase A (P ready)
__device__ unsigned g_cntB[8];     // per K-group: blocks done with phase B (H ready)

// ---------------------------------------------------------------------------
// helpers
// ---------------------------------------------------------------------------
__device__ __forceinline__ float tf32r(float x) {
    unsigned u;
    asm("cvt.rna.tf32.f32 %0, %1;" : "=r"(u) : "f"(x));
    return __uint_as_float(u);
}

__device__ __forceinline__ void mma8(float (&c)[4], const float (&a)[4], float b0, float b1) {
    unsigned a0 = __float_as_uint(a[0]), a1 = __float_as_uint(a[1]);
    unsigned a2 = __float_as_uint(a[2]), a3 = __float_as_uint(a[3]);
    unsigned B0 = __float_as_uint(b0),  B1 = __float_as_uint(b1);
    asm volatile(
        "mma.sync.aligned.m16n8k8.row.col.f32.tf32.tf32.f32 "
        "{%0,%1,%2,%3}, {%4,%5,%6,%7}, {%8,%9}, {%0,%1,%2,%3};\n"
        : "+f"(c[0]), "+f"(c[1]), "+f"(c[2]), "+f"(c[3])
        : "r"(a0), "r"(a1), "r"(a2), "r"(a3), "r"(B0), "r"(B1));
}

__device__ __forceinline__ float sigmoidf_(float x) { return 1.f / (1.f + __expf(-x)); }

__device__ __forceinline__ void cpasync16(uint32_t daddr, const float* gptr) {
    asm volatile("cp.async.cg.shared.global [%0], [%1], 16;\n"
                 :: "r"(daddr), "l"(gptr) : "memory");
}
__device__ __forceinline__ void cpasync_commit() {
    asm volatile("cp.async.commit_group;\n" ::: "memory");
}
__device__ __forceinline__ void cpasync_wait2() {
    asm volatile("cp.async.wait_group 2;\n" ::: "memory");
}
__device__ __forceinline__ void cpasync_wait1() {
    asm volatile("cp.async.wait_group 1;\n" ::: "memory");
}
__device__ __forceinline__ void cpasync_wait0() {
    asm volatile("cp.async.wait_group 0;\n" ::: "memory");
}

// spin until *p >= target (acquire; gpu scope)
__device__ __forceinline__ void spin_ge(const unsigned* p, unsigned target) {
    unsigned cur;
    do {
        asm volatile("ld.acquire.gpu.global.u32 %0, [%1];"
                     : "=r"(cur) : "l"(p) : "memory");
    } while ((int)(cur - target) < 0);
}

__device__ __forceinline__ void release_add(unsigned* p) {
    asm volatile("red.release.gpu.global.add.u32 [%0], %1;"
                 :: "l"(p), "r"(1u) : "memory");
}

// Full grid barrier — used ONCE (after init).
__device__ __forceinline__ void gridbar() {
    __syncthreads();
    if (threadIdx.x == 0) {
        unsigned gen;
        asm volatile("ld.relaxed.gpu.global.u32 %0, [%1];"
                     : "=r"(gen) : "l"(&g_bar_gen) : "memory");
        unsigned old;
        asm volatile("atom.acq_rel.gpu.global.add.u32 %0, [%1], 1;"
                     : "=r"(old) : "l"(&g_bar_count) : "memory");
        if (old == NBLK - 1) {
            asm volatile("st.relaxed.gpu.global.u32 [%0], %1;"
                         :: "l"(&g_bar_count), "r"(0u) : "memory");
            asm volatile("st.release.gpu.global.u32 [%0], %1;"
                         :: "l"(&g_bar_gen), "r"(gen + 1) : "memory");
        } else {
            unsigned cur;
            do {
                asm volatile("ld.acquire.gpu.global.u32 %0, [%1];"
                             : "=r"(cur) : "l"(&g_bar_gen) : "memory");
            } while (cur == gen);
        }
    }
    __syncthreads();
}

// ---------------------------------------------------------------------------
// MMA phase, chunk-gated dataflow version.
//   Chunk order rotated to start at own group g0; each chunk's cp.async is
//   gated on cnt[group] >= target (group fully published by its 16 producers).
//   Tail wait_group counts fixed (R10 had a latent race at the last 2 chunks).
// ---------------------------------------------------------------------------
template<int NT>
__device__ __forceinline__ void mma_phase(
    const float* __restrict__ src,
    const float* __restrict__ sW,
    float* __restrict__ sA,
    float (&acc)[NT][4],
    const unsigned* __restrict__ cnt, unsigned target, int g0,
    int tid, int lane, int mt, int kq, int gid, int tg)
{
#pragma unroll
    for (int nt = 0; nt < NT; ++nt)
#pragma unroll
        for (int e = 0; e < 4; ++e) acc[nt][e] = 0.f;

    const int crow = tid >> 5;          // row within 16-row slab
    const int ckw  = tid & 31;          // float4 col within 128-col chunk

    uint32_t sbase = (uint32_t)__cvta_generic_to_shared(sA);

    // prologue: gate + issue chunks it=0..NSTG-1
    if (tid == 0) {
#pragma unroll
        for (int i = 0; i < NSTG; ++i) spin_ge(&cnt[(g0 + i) & 7], target);
    }
    __syncthreads();
#pragma unroll
    for (int i = 0; i < NSTG; ++i) {
        int c = (g0 + i) & 7;
#pragma unroll
        for (int j = 0; j < 4; ++j) {
            int row = j * 16 + crow;
            uint32_t d = sbase + (i * (64 * SAPAD) + row * SAPAD + ckw * 4) * 4;
            cpasync16(d, src + (size_t)row * HID + c * CH + ckw * 4);
        }
        cpasync_commit();
    }

    for (int it = 0; it < NCH; ++it) {
        if (it + 2 < NCH)      cpasync_wait2();
        else if (it + 1 < NCH) cpasync_wait1();
        else                   cpasync_wait0();
        __syncthreads();

        int c = (g0 + it) & 7;
        const float* aBase = sA + (it % NSTG) * (64 * SAPAD) + (mt * 16 + gid) * SAPAD;
#pragma unroll
        for (int i = 0; i < 4; ++i) {
            int k8l = kq * 4 + i;
            int kb  = k8l * 8;
            float a[4];
            a[0] = tf32r(aBase[kb + tg]);
            a[1] = tf32r(aBase[8 * SAPAD + kb + tg]);
            a[2] = tf32r(aBase[kb + 4 + tg]);
            a[3] = tf32r(aBase[8 * SAPAD + kb + 4 + tg]);
            int k8g = c * 16 + k8l;
#pragma unroll
            for (int nt = 0; nt < NT; ++nt) {
                float2 b = *reinterpret_cast<const float2*>(sW + ((k8g * NT + nt) * 32 + lane) * 2);
                mma8(acc[nt], a, b.x, b.y);
            }
        }

        // gate the next chunk (overlaps other warps' compute), then refill
        if (tid == 0 && it + NSTG < NCH)
            spin_ge(&cnt[(g0 + it + NSTG) & 7], target);
        __syncthreads();
        if (it + NSTG < NCH) {
            int c2 = (g0 + it + NSTG) & 7;
#pragma unroll
            for (int j = 0; j < 4; ++j) {
                int row = j * 16 + crow;
                uint32_t d = sbase + ((it % NSTG) * (64 * SAPAD) + row * SAPAD + ckw * 4) * 4;
                cpasync16(d, src + (size_t)row * HID + c2 * CH + ckw * 4);
            }
            cpasync_commit();
        }
    }
}

// ---------------------------------------------------------------------------
// Persistent recurrence: 128 blocks x 512 threads; block b owns cols
// [8b, 8b+8) of ALL THREE gates. No grid barriers in the loop — per-group
// release/acquire counters gate each K-chunk.
// ---------------------------------------------------------------------------
__global__ void __launch_bounds__(NTHR, 1)
gru_persist(const int* __restrict__ X,
            const float* __restrict__ Wz, const float* __restrict__ bz,
            const float* __restrict__ Wr, const float* __restrict__ br,
            const float* __restrict__ Wh, const float* __restrict__ bh)
{
    extern __shared__ float sm[];
    float* sWa  = sm;                        // 16384 : z|r weights (b-frag packed)
    float* sWh  = sWa + 16384;               //  8192 : h weights
    float* sA   = sWh + 8192;                // 25344 : A ring [3][64][SAPAD]
    float* sRed = sA + NSTG * 64 * SAPAD;    //  4096 : K-quarter partials
    float* sZ   = sRed + 4096;               //   512 : z gate [64][8]
    int*   sXi  = reinterpret_cast<int*>(sZ + 512);  // 64 token ids

    const int tid  = threadIdx.x;
    const int bid  = blockIdx.x;
    const int lane = tid & 31;
    const int wid  = tid >> 5;
    const int mt   = wid >> 2;
    const int kq   = wid & 3;
    const int gid  = lane >> 2;
    const int tg   = lane & 3;
    const int n0   = bid * 8;
    const int g0   = bid >> 4;         // own K-group (cols n0 are inside it)

    // pack weights -> b-fragment layout (tf32-rounded), once per launch
    for (int e = tid; e < 16384; e += NTHR) {
        int reg = e & 1, ln = (e >> 1) & 31, nt = (e >> 6) & 1, k8 = e >> 7;
        int k   = k8 * 8 + reg * 4 + (ln & 3);
        int col = n0 + (ln >> 2);
        const float* W = nt ? Wr : Wz;
        sWa[e] = tf32r(W[(size_t)(VOCAB + k) * HID + col]);
    }
    for (int e = tid; e < 8192; e += NTHR) {
        int reg = e & 1, ln = (e >> 1) & 31, k8 = e >> 6;
        int k   = k8 * 8 + reg * 4 + (ln & 3);
        int col = n0 + (ln >> 2);
        sWh[e] = tf32r(Wh[(size_t)(VOCAB + k) * HID + col]);
    }

    // zero H0 + reset counters (graph replays reuse device globals!)
    g_H[bid * NTHR + tid] = 0.f;
    if (bid == 0 && tid < 16) {
        unsigned* c = (tid < 8) ? &g_cntA[tid] : &g_cntB[tid - 8];
        asm volatile("st.relaxed.gpu.global.u32 [%0], %1;" :: "l"(c), "r"(0u) : "memory");
    }
    gridbar();   // the only full-grid barrier

    for (int t = 0; t < SEQ; ++t) {
        const float* Hc = g_H + (size_t)t * (BATCH * HID);
        float*       Hn = g_H + (size_t)(t + 1) * (BATCH * HID);

        if (tid < BATCH) sXi[tid] = X[tid * SEQ + t];

        // ================= Phase A: z and r for cols [n0, n0+8) =================
        {
            float acc[2][4];
            // H(t) chunks gated on g_cntB >= 16*t  (t=0: trivially satisfied)
            mma_phase<2>(Hc, sWa, sA, acc, g_cntB, 16u * (unsigned)t, g0,
                         tid, lane, mt, kq, gid, tg);

            if (kq != 0) {
#pragma unroll
                for (int nt = 0; nt < 2; ++nt)
                    *reinterpret_cast<float4*>(sRed + (((kq * 4 + mt) * 2 + nt) * 32 + lane) * 4) =
                        make_float4(acc[nt][0], acc[nt][1], acc[nt][2], acc[nt][3]);
            }
            __syncthreads();
            if (kq == 0) {
#pragma unroll
                for (int nt = 0; nt < 2; ++nt)
#pragma unroll
                    for (int q = 1; q < 4; ++q) {
                        float4 p = *reinterpret_cast<const float4*>(
                            sRed + (((q * 4 + mt) * 2 + nt) * 32 + lane) * 4);
                        acc[nt][0] += p.x; acc[nt][1] += p.y;
                        acc[nt][2] += p.z; acc[nt][3] += p.w;
                    }
#pragma unroll
                for (int half = 0; half < 2; ++half) {
                    int row = mt * 16 + gid + half * 8;
                    int x   = sXi[row];
                    int n   = n0 + tg * 2;
                    size_t widx = (size_t)x * HID + n;
                    int idx = row * HID + n;
                    float2 wz2 = *reinterpret_cast<const float2*>(Wz + widx);
                    float2 bz2 = *reinterpret_cast<const float2*>(bz + n);
                    float z0 = sigmoidf_(acc[0][half * 2 + 0] + wz2.x + bz2.x);
                    float z1 = sigmoidf_(acc[0][half * 2 + 1] + wz2.y + bz2.y);
                    *reinterpret_cast<float2*>(sZ + row * 8 + tg * 2) = make_float2(z0, z1);
                    float2 wr2 = *reinterpret_cast<const float2*>(Wr + widx);
                    float2 br2 = *reinterpret_cast<const float2*>(br + n);
                    float r0 = sigmoidf_(acc[1][half * 2 + 0] + wr2.x + br2.x);
                    float r1 = sigmoidf_(acc[1][half * 2 + 1] + wr2.y + br2.y);
                    float2 h2 = __ldcg(reinterpret_cast<const float2*>(Hc + idx));
                    __stcg(reinterpret_cast<float2*>(g_P + idx),
                           make_float2(r0 * h2.x, r1 * h2.y));
                }
            }
            __syncthreads();
            if (tid == 0) release_add(&g_cntA[g0]);   // publish P cols [n0,n0+8)
        }

        // ================= Phase B: h gate + H update =================
        {
            float acc[1][4];
            // P(t) chunks gated on g_cntA >= 16*(t+1)
            mma_phase<1>(g_P, sWh, sA, acc, g_cntA, 16u * (unsigned)(t + 1), g0,
                         tid, lane, mt, kq, gid, tg);

            if (kq != 0) {
                *reinterpret_cast<float4*>(sRed + ((kq * 4 + mt) * 32 + lane) * 4) =
                    make_float4(acc[0][0], acc[0][1], acc[0][2], acc[0][3]);
            }
            __syncthreads();
            if (kq == 0) {
#pragma unroll
                for (int q = 1; q < 4; ++q) {
                    float4 p = *reinterpret_cast<const float4*>(
                        sRed + ((q * 4 + mt) * 32 + lane) * 4);
                    acc[0][0] += p.x; acc[0][1] += p.y;
                    acc[0][2] += p.z; acc[0][3] += p.w;
                }
#pragma unroll
                for (int half = 0; half < 2; ++half) {
                    int row = mt * 16 + gid + half * 8;
                    int x   = sXi[row];
                    int n   = n0 + tg * 2;
                    size_t widx = (size_t)x * HID + n;
                    int idx = row * HID + n;
                    float2 wh2 = *reinterpret_cast<const float2*>(Wh + widx);
                    float2 bh2 = *reinterpret_cast<const float2*>(bh + n);
                    float h0 = tanhf(acc[0][half * 2 + 0] + wh2.x + bh2.x);
                    float h1 = tanhf(acc[0][half * 2 + 1] + wh2.y + bh2.y);
                    float2 z2  = *reinterpret_cast<const float2*>(sZ + row * 8 + tg * 2);
                    float2 hc2 = __ldcg(reinterpret_cast<const float2*>(Hc + idx));
                    __stcg(reinterpret_cast<float2*>(Hn + idx),
                           make_float2(z2.x * h0 + (1.f - z2.x) * hc2.x,
                                       z2.y * h1 + (1.f - z2.y) * hc2.y));
                }
            }
            __syncthreads();
            if (tid == 0) release_add(&g_cntB[g0]);   // publish H(t+1) cols [n0,n0+8)
        }
    }
}

// ---------------------------------------------------------------------------
// Output GEMM: Y = H_all[16384 x 1024] @ Wo[1024 x 4096] + bo
//   128x64 block tile, 256 threads (8 warps: 4 m-rows x 2 n-cols).
// ---------------------------------------------------------------------------
__global__ void __launch_bounds__(256)
gru_out2(const float* __restrict__ Wo, const float* __restrict__ bo,
         float* __restrict__ out)
{
    __shared__ float As[128 * 36];
    __shared__ float Bs[32 * 72];

    const int n0 = blockIdx.x * 64;
    const int m0 = blockIdx.y * 128;
    const float* A  = g_H + (size_t)(BATCH * HID) + (size_t)m0 * HID;
    const float* B0 = Wo + n0;
    const float* B1 = Wo + n0 + 32;

    const int tid = threadIdx.x, lane = tid & 31, w = tid >> 5;
    const int wm = w >> 1, wn = w & 1, gid = lane >> 2, tg = lane & 3;

    float acc[2][4][4];
#pragma unroll
    for (int mi = 0; mi < 2; ++mi)
#pragma unroll
        for (int ni = 0; ni < 4; ++ni)
#pragma unroll
            for (int e = 0; e < 4; ++e) acc[mi][ni][e] = 0.f;

    float4 ra[4]; float4 rb[2];
#pragma unroll
    for (int j = 0; j < 4; ++j) {
        int i = tid + j * 256, row = i >> 3, kq8 = i & 7;
        ra[j] = *reinterpret_cast<const float4*>(A + (size_t)row * HID + kq8 * 4);
    }
#pragma unroll
    for (int j = 0; j < 2; ++j) {
        int i = tid + j * 256, row = i >> 4, nq = i & 15, c4 = nq * 4;
        const float* src = (c4 < 32) ? (B0 + (size_t)row * VOCAB + c4)
                                     : (B1 + (size_t)row * VOCAB + (c4 - 32));
        rb[j] = *reinterpret_cast<const float4*>(src);
    }

    for (int kk = 0; kk < HID; kk += 32) {
#pragma unroll
        for (int j = 0; j < 4; ++j) {
            int i = tid + j * 256, row = i >> 3, kq8 = i & 7;
            float4 v; v.x = tf32r(ra[j].x); v.y = tf32r(ra[j].y);
            v.z = tf32r(ra[j].z); v.w = tf32r(ra[j].w);
            *reinterpret_cast<float4*>(As + row * 36 + kq8 * 4) = v;
        }
#pragma unroll
        for (int j = 0; j < 2; ++j) {
            int i = tid + j * 256, row = i >> 4, nq = i & 15;
            float4 v; v.x = tf32r(rb[j].x); v.y = tf32r(rb[j].y);
            v.z = tf32r(rb[j].z); v.w = tf32r(rb[j].w);
            *reinterpret_cast<float4*>(Bs + row * 72 + nq * 4) = v;
        }
        __syncthreads();
        if (kk + 32 < HID) {
#pragma unroll
            for (int j = 0; j < 4; ++j) {
                int i = tid + j * 256, row = i >> 3, kq8 = i & 7;
                ra[j] = *reinterpret_cast<const float4*>(A + (size_t)row * HID + kk + 32 + kq8 * 4);
            }
#pragma unroll
            for (int j = 0; j < 2; ++j) {
                int i = tid + j * 256, row = i >> 4, nq = i & 15, c4 = nq * 4;
                const float* src = (c4 < 32)
                    ? (B0 + (size_t)(kk + 32 + row) * VOCAB + c4)
                    : (B1 + (size_t)(kk + 32 + row) * VOCAB + (c4 - 32));
                rb[j] = *reinterpret_cast<const float4*>(src);
            }
        }
#pragma unroll
        for (int k8 = 0; k8 < 4; ++k8) {
            int kb = k8 * 8;
            float a[2][4];
#pragma unroll
            for (int mi = 0; mi < 2; ++mi) {
                int rb0 = wm * 32 + mi * 16;
                a[mi][0] = As[(rb0 + gid) * 36 + kb + tg];
                a[mi][1] = As[(rb0 + 8 + gid) * 36 + kb + tg];
                a[mi][2] = As[(rb0 + gid) * 36 + kb + 4 + tg];
                a[mi][3] = As[(rb0 + 8 + gid) * 36 + kb + 4 + tg];
            }
#pragma unroll
            for (int ni = 0; ni < 4; ++ni) {
                int col = wn * 32 + ni * 8 + gid;
                float b0 = Bs[(kb + tg) * 72 + col];
                float b1 = Bs[(kb + 4 + tg) * 72 + col];
#pragma unroll
                for (int mi = 0; mi < 2; ++mi) mma8(acc[mi][ni], a[mi], b0, b1);
            }
        }
        __syncthreads();
    }

#pragma unroll
    for (int mi = 0; mi < 2; ++mi)
#pragma unroll
        for (int half = 0; half < 2; ++half) {
            int row = m0 + wm * 32 + mi * 16 + half * 8 + gid;
#pragma unroll
            for (int ni = 0; ni < 4; ++ni)
#pragma unroll
                for (int e = 0; e < 2; ++e) {
                    int n = n0 + wn * 32 + ni * 8 + tg * 2 + e;
                    out[(size_t)row * VOCAB + n] = acc[mi][ni][half * 2 + e] + bo[n];
                }
        }
}

__global__ void gru_copy_hfinal(float* __restrict__ dst) {
    int i = blockIdx.x * blockDim.x + threadIdx.x;
    if (i < BATCH * HID) dst[i] = g_H[(size_t)SEQ * (BATCH * HID) + i];
}

// ---------------------------------------------------------------------------
extern "C" void kernel_launch(void* const* d_in, const int* in_sizes, int n_in,
                              void* d_out, int out_size)
{
    const int*   X  = (const int*)  d_in[0];
    const float* Wz = (const float*)d_in[1];
    const float* bz = (const float*)d_in[2];
    const float* Wr = (const float*)d_in[3];
    const float* br = (const float*)d_in[4];
    const float* Wh = (const float*)d_in[5];
    const float* bh = (const float*)d_in[6];
    const float* Wo = (const float*)d_in[7];
    const float* bo = (const float*)d_in[8];
    float* out = (float*)d_out;

    const int smemFloats = 16384 + 8192 + NSTG * 64 * SAPAD + 4096 + 512 + 64;
    const int smemBytes  = smemFloats * 4;   // 218368 B
    cudaFuncSetAttribute(gru_persist, cudaFuncAttributeMaxDynamicSharedMemorySize, smemBytes);

    gru_persist<<<NBLK, NTHR, smemBytes>>>(X, Wz, bz, Wr, br, Wh, bh);

    gru_out2<<<dim3(VOCAB / 64, (SEQ * BATCH) / 128), 256>>>(Wo, bo, out);

    const long long ybytes = (long long)SEQ * BATCH * VOCAB;
    if ((long long)out_size >= ybytes + (long long)BATCH * HID) {
        gru_copy_hfinal<<<64, 1024>>>(out + ybytes);
    }
    (void)in_sizes; (void)n_in;
}

// round 12
// speedup vs baseline: 1.3102x; 1.3102x over previous
#include <cuda_runtime.h>
#include <cstdint>

#define BATCH  64
#define HID    1024
#define VOCAB  4096
#define SEQ    256
#define NBLK   128
#define NTHR   512
#define CH     128                 // A-chunk width (cols of K)
#define NCH    (HID / CH)          // 8 chunks
#define SAPAD  132                 // padded row stride for sA
#define NSTG   3                   // cp.async pipeline stages
#define RSTR   36                  // sRed row stride (8 cols * 4 kq + 4 pad)

// ---------------------------------------------------------------------------
// Global scratch
// ---------------------------------------------------------------------------
__device__ float g_H[(SEQ + 1) * BATCH * HID];
__device__ float g_P[BATCH * HID];
__device__ unsigned g_bar_count = 0;
__device__ unsigned g_bar_gen   = 0;

// ---------------------------------------------------------------------------
// helpers
// ---------------------------------------------------------------------------
__device__ __forceinline__ float tf32r(float x) {
    unsigned u;
    asm("cvt.rna.tf32.f32 %0, %1;" : "=r"(u) : "f"(x));
    return __uint_as_float(u);
}

__device__ __forceinline__ void mma8(float (&c)[4], const float (&a)[4], float b0, float b1) {
    unsigned a0 = __float_as_uint(a[0]), a1 = __float_as_uint(a[1]);
    unsigned a2 = __float_as_uint(a[2]), a3 = __float_as_uint(a[3]);
    unsigned B0 = __float_as_uint(b0),  B1 = __float_as_uint(b1);
    asm volatile(
        "mma.sync.aligned.m16n8k8.row.col.f32.tf32.tf32.f32 "
        "{%0,%1,%2,%3}, {%4,%5,%6,%7}, {%8,%9}, {%0,%1,%2,%3};\n"
        : "+f"(c[0]), "+f"(c[1]), "+f"(c[2]), "+f"(c[3])
        : "r"(a0), "r"(a1), "r"(a2), "r"(a3), "r"(B0), "r"(B1));
}

__device__ __forceinline__ float sigmoidf_(float x) { return 1.f / (1.f + __expf(-x)); }

__device__ __forceinline__ void cpasync16(uint32_t daddr, const float* gptr) {
    asm volatile("cp.async.cg.shared.global [%0], [%1], 16;\n"
                 :: "r"(daddr), "l"(gptr) : "memory");
}
__device__ __forceinline__ void cpasync_commit() {
    asm volatile("cp.async.commit_group;\n" ::: "memory");
}
template<int N>
__device__ __forceinline__ void cpasync_wait() {
    asm volatile("cp.async.wait_group %0;\n" :: "n"(N) : "memory");
}

// Light release/acquire grid barrier (thread 0 only touches global).
__device__ __forceinline__ void gridbar() {
    __syncthreads();
    if (threadIdx.x == 0) {
        unsigned gen;
        asm volatile("ld.relaxed.gpu.global.u32 %0, [%1];"
                     : "=r"(gen) : "l"(&g_bar_gen) : "memory");
        unsigned old;
        asm volatile("atom.acq_rel.gpu.global.add.u32 %0, [%1], 1;"
                     : "=r"(old) : "l"(&g_bar_count) : "memory");
        if (old == NBLK - 1) {
            asm volatile("st.relaxed.gpu.global.u32 [%0], %1;"
                         :: "l"(&g_bar_count), "r"(0u) : "memory");
            asm volatile("st.release.gpu.global.u32 [%0], %1;"
                         :: "l"(&g_bar_gen), "r"(gen + 1) : "memory");
        } else {
            unsigned cur;
            do {
                asm volatile("ld.acquire.gpu.global.u32 %0, [%1];"
                             : "=r"(cur) : "l"(&g_bar_gen) : "memory");
            } while (cur == gen);
        }
    }
    __syncthreads();
}

// ---------------------------------------------------------------------------
// Persistent recurrence: 128 blocks x 512 threads; block b owns cols
// [8b, 8b+8) of ALL THREE gates. R10 pipeline + race fix + wide epilogue.
// ---------------------------------------------------------------------------
__global__ void __launch_bounds__(NTHR, 1)
gru_persist(const int* __restrict__ X,
            const float* __restrict__ Wz, const float* __restrict__ bz,
            const float* __restrict__ Wr, const float* __restrict__ br,
            const float* __restrict__ Wh, const float* __restrict__ bh)
{
    extern __shared__ float sm[];
    float* sWa  = sm;                        // 16384 : z|r weights (float4 frag)
    float* sWh  = sWa + 16384;               //  8192 : h weights (float2 frag)
    float* sA   = sWh + 8192;                // 25344 : A ring [3][64][SAPAD]
    float* sRed = sA + NSTG * 64 * SAPAD;    //  4608 : partials [gate][row][col][kq]
    float* sZ   = sRed + 2 * 64 * RSTR;      //   512 : z gate [64][8]
    float* sHc  = sZ + 512;                  //   512 : own-col H(t) [64][8]
    int*   sXi  = reinterpret_cast<int*>(sHc + 512);  // 64 token ids

    const int tid  = threadIdx.x;
    const int bid  = blockIdx.x;
    const int lane = tid & 31;
    const int wid  = tid >> 5;
    const int mt   = wid >> 2;
    const int kq   = wid & 3;
    const int gid  = lane >> 2;
    const int tg   = lane & 3;
    const int n0   = bid * 8;
    const int g0   = bid >> 4;               // chunk containing own columns
    const int lcol = 8 * (bid & 15);         // own-col offset inside chunk g0

    // epilogue thread mapping (all 512 threads)
    const int erow = tid >> 3;
    const int ecol = tid & 7;
    const int en   = n0 + ecol;

    // copy coords
    const int crow = tid >> 5;
    const int ckw  = tid & 31;
    uint32_t sbase = (uint32_t)__cvta_generic_to_shared(sA);

    // ---- pack weights once: phase A float4 {z.b0,z.b1,r.b0,r.b1} ----
    for (int e = tid; e < 16384; e += NTHR) {
        int c = e & 3, ln = (e >> 2) & 31, k8 = e >> 7;
        int k   = k8 * 8 + (c & 1) * 4 + (ln & 3);
        int col = n0 + (ln >> 2);
        const float* W = (c >> 1) ? Wr : Wz;
        sWa[e] = tf32r(W[(size_t)(VOCAB + k) * HID + col]);
    }
    for (int e = tid; e < 8192; e += NTHR) {
        int reg = e & 1, ln = (e >> 1) & 31, k8 = e >> 6;
        int k   = k8 * 8 + reg * 4 + (ln & 3);
        int col = n0 + (ln >> 2);
        sWh[e] = tf32r(Wh[(size_t)(VOCAB + k) * HID + col]);
    }

    // bias preload (thread-fixed columns)
    const float bzv = bz[en], brv = br[en], bhv = bh[en];

    // zero H0
    g_H[bid * NTHR + tid] = 0.f;
    gridbar();

    for (int t = 0; t < SEQ; ++t) {
        const float* Hc = g_H + (size_t)t * (BATCH * HID);
        float*       Hn = g_H + (size_t)(t + 1) * (BATCH * HID);

        if (tid < BATCH) sXi[tid] = X[tid * SEQ + t];
        __syncthreads();

        // prefetch the gather operands for both epilogues (consumed ~8 chunks later)
        const int x = sXi[erow];
        const size_t wix = (size_t)x * HID + en;
        const float wzv = __ldg(Wz + wix);
        const float wrv = __ldg(Wr + wix);
        const float whv = __ldg(Wh + wix);

        // ================= Phase A: z and r =================
        {
            float az[4] = {0,0,0,0}, ar[4] = {0,0,0,0};

            // prologue: chunks 0..2
#pragma unroll
            for (int c = 0; c < NSTG; ++c) {
#pragma unroll
                for (int j = 0; j < 4; ++j) {
                    int row = j * 16 + crow;
                    uint32_t d = sbase + (c * (64 * SAPAD) + row * SAPAD + ckw * 4) * 4;
                    cpasync16(d, Hc + (size_t)row * HID + c * CH + ckw * 4);
                }
                cpasync_commit();
            }

#pragma unroll
            for (int it = 0; it < NCH; ++it) {
                if (it + 2 < NCH)      cpasync_wait<2>();
                else if (it + 1 < NCH) cpasync_wait<1>();
                else                   cpasync_wait<0>();
                __syncthreads();

                const float* stg = sA + (it % NSTG) * (64 * SAPAD);
                if (it == g0) sHc[tid] = stg[erow * SAPAD + lcol + ecol];

                const float* aBase = stg + (mt * 16 + gid) * SAPAD;
#pragma unroll
                for (int i = 0; i < 4; ++i) {
                    int k8l = kq * 4 + i;
                    int kb  = k8l * 8;
                    float a[4];
                    a[0] = tf32r(aBase[kb + tg]);
                    a[1] = tf32r(aBase[8 * SAPAD + kb + tg]);
                    a[2] = tf32r(aBase[kb + 4 + tg]);
                    a[3] = tf32r(aBase[8 * SAPAD + kb + 4 + tg]);
                    int k8g = it * 16 + k8l;
                    float4 w = *reinterpret_cast<const float4*>(sWa + (k8g * 32 + lane) * 4);
                    mma8(az, a, w.x, w.y);
                    mma8(ar, a, w.z, w.w);
                }
                __syncthreads();

                if (it + NSTG < NCH) {
                    int c = it + NSTG;
#pragma unroll
                    for (int j = 0; j < 4; ++j) {
                        int row = j * 16 + crow;
                        uint32_t d = sbase + ((it % NSTG) * (64 * SAPAD) + row * SAPAD + ckw * 4) * 4;
                        cpasync16(d, Hc + (size_t)row * HID + c * CH + ckw * 4);
                    }
                    cpasync_commit();
                }
            }

            // partials: all warps -> sRed[gate][row][col][kq]
#pragma unroll
            for (int j = 0; j < 4; ++j) {
                int prow = mt * 16 + gid + (j >> 1) * 8;
                int pcol = tg * 2 + (j & 1);
                sRed[prow * RSTR + pcol * 4 + kq]            = az[j];
                sRed[64 * RSTR + prow * RSTR + pcol * 4 + kq] = ar[j];
            }
            __syncthreads();

            // wide epilogue: one (row,col) per thread
            {
                float4 zp = *reinterpret_cast<const float4*>(sRed + erow * RSTR + ecol * 4);
                float4 rp = *reinterpret_cast<const float4*>(sRed + 64 * RSTR + erow * RSTR + ecol * 4);
                float zsum = ((zp.x + zp.y) + zp.z) + zp.w;
                float rsum = ((rp.x + rp.y) + rp.z) + rp.w;
                float zv = sigmoidf_(zsum + wzv + bzv);
                float rv = sigmoidf_(rsum + wrv + brv);
                sZ[tid] = zv;
                __stcg(g_P + erow * HID + en, rv * sHc[tid]);
            }
        }
        gridbar();

        // ================= Phase B: h gate + H update =================
        {
            float ah[4] = {0,0,0,0};

#pragma unroll
            for (int c = 0; c < NSTG; ++c) {
#pragma unroll
                for (int j = 0; j < 4; ++j) {
                    int row = j * 16 + crow;
                    uint32_t d = sbase + (c * (64 * SAPAD) + row * SAPAD + ckw * 4) * 4;
                    cpasync16(d, g_P + (size_t)row * HID + c * CH + ckw * 4);
                }
                cpasync_commit();
            }

#pragma unroll
            for (int it = 0; it < NCH; ++it) {
                if (it + 2 < NCH)      cpasync_wait<2>();
                else if (it + 1 < NCH) cpasync_wait<1>();
                else                   cpasync_wait<0>();
                __syncthreads();

                const float* aBase = sA + (it % NSTG) * (64 * SAPAD) + (mt * 16 + gid) * SAPAD;
#pragma unroll
                for (int i = 0; i < 4; ++i) {
                    int k8l = kq * 4 + i;
                    int kb  = k8l * 8;
                    float a[4];
                    a[0] = tf32r(aBase[kb + tg]);
                    a[1] = tf32r(aBase[8 * SAPAD + kb + tg]);
                    a[2] = tf32r(aBase[kb + 4 + tg]);
                    a[3] = tf32r(aBase[8 * SAPAD + kb + 4 + tg]);
                    int k8g = it * 16 + k8l;
                    float2 b = *reinterpret_cast<const float2*>(sWh + (k8g * 32 + lane) * 2);
                    mma8(ah, a, b.x, b.y);
                }
                __syncthreads();

                if (it + NSTG < NCH) {
                    int c = it + NSTG;
#pragma unroll
                    for (int j = 0; j < 4; ++j) {
                        int row = j * 16 + crow;
                        uint32_t d = sbase + ((it % NSTG) * (64 * SAPAD) + row * SAPAD + ckw * 4) * 4;
                        cpasync16(d, g_P + (size_t)row * HID + c * CH + ckw * 4);
                    }
                    cpasync_commit();
                }
            }

#pragma unroll
            for (int j = 0; j < 4; ++j) {
                int prow = mt * 16 + gid + (j >> 1) * 8;
                int pcol = tg * 2 + (j & 1);
                sRed[prow * RSTR + pcol * 4 + kq] = ah[j];
            }
            __syncthreads();

            {
                float4 hp = *reinterpret_cast<const float4*>(sRed + erow * RSTR + ecol * 4);
                float hsum = ((hp.x + hp.y) + hp.z) + hp.w;
                float hv = tanhf(hsum + whv + bhv);
                float zv = sZ[tid];
                float hc = sHc[tid];
                __stcg(Hn + erow * HID + en, zv * hv + (1.f - zv) * hc);
            }
        }
        gridbar();
    }
}

// ---------------------------------------------------------------------------
// Output GEMM: Y = H_all[16384 x 1024] @ Wo[1024 x 4096] + bo
//   128x64 block tile, 256 threads (known-good R10 version).
// ---------------------------------------------------------------------------
__global__ void __launch_bounds__(256)
gru_out2(const float* __restrict__ Wo, const float* __restrict__ bo,
         float* __restrict__ out)
{
    __shared__ float As[128 * 36];
    __shared__ float Bs[32 * 72];

    const int n0 = blockIdx.x * 64;
    const int m0 = blockIdx.y * 128;
    const float* A  = g_H + (size_t)(BATCH * HID) + (size_t)m0 * HID;
    const float* B0 = Wo + n0;
    const float* B1 = Wo + n0 + 32;

    const int tid = threadIdx.x, lane = tid & 31, w = tid >> 5;
    const int wm = w >> 1, wn = w & 1, gid = lane >> 2, tg = lane & 3;

    float acc[2][4][4];
#pragma unroll
    for (int mi = 0; mi < 2; ++mi)
#pragma unroll
        for (int ni = 0; ni < 4; ++ni)
#pragma unroll
            for (int e = 0; e < 4; ++e) acc[mi][ni][e] = 0.f;

    float4 ra[4]; float4 rb[2];
#pragma unroll
    for (int j = 0; j < 4; ++j) {
        int i = tid + j * 256, row = i >> 3, kq8 = i & 7;
        ra[j] = *reinterpret_cast<const float4*>(A + (size_t)row * HID + kq8 * 4);
    }
#pragma unroll
    for (int j = 0; j < 2; ++j) {
        int i = tid + j * 256, row = i >> 4, nq = i & 15, c4 = nq * 4;
        const float* src = (c4 < 32) ? (B0 + (size_t)row * VOCAB + c4)
                                     : (B1 + (size_t)row * VOCAB + (c4 - 32));
        rb[j] = *reinterpret_cast<const float4*>(src);
    }

    for (int kk = 0; kk < HID; kk += 32) {
#pragma unroll
        for (int j = 0; j < 4; ++j) {
            int i = tid + j * 256, row = i >> 3, kq8 = i & 7;
            float4 v; v.x = tf32r(ra[j].x); v.y = tf32r(ra[j].y);
            v.z = tf32r(ra[j].z); v.w = tf32r(ra[j].w);
            *reinterpret_cast<float4*>(As + row * 36 + kq8 * 4) = v;
        }
#pragma unroll
        for (int j = 0; j < 2; ++j) {
            int i = tid + j * 256, row = i >> 4, nq = i & 15;
            float4 v; v.x = tf32r(rb[j].x); v.y = tf32r(rb[j].y);
            v.z = tf32r(rb[j].z); v.w = tf32r(rb[j].w);
            *reinterpret_cast<float4*>(Bs + row * 72 + nq * 4) = v;
        }
        __syncthreads();
        if (kk + 32 < HID) {
#pragma unroll
            for (int j = 0; j < 4; ++j) {
                int i = tid + j * 256, row = i >> 3, kq8 = i & 7;
                ra[j] = *reinterpret_cast<const float4*>(A + (size_t)row * HID + kk + 32 + kq8 * 4);
            }
#pragma unroll
            for (int j = 0; j < 2; ++j) {
                int i = tid + j * 256, row = i >> 4, nq = i & 15, c4 = nq * 4;
                const float* src = (c4 < 32)
                    ? (B0 + (size_t)(kk + 32 + row) * VOCAB + c4)
                    : (B1 + (size_t)(kk + 32 + row) * VOCAB + (c4 - 32));
                rb[j] = *reinterpret_cast<const float4*>(src);
            }
        }
#pragma unroll
        for (int k8 = 0; k8 < 4; ++k8) {
            int kb = k8 * 8;
            float a[2][4];
#pragma unroll
            for (int mi = 0; mi < 2; ++mi) {
                int rb0 = wm * 32 + mi * 16;
                a[mi][0] = As[(rb0 + gid) * 36 + kb + tg];
                a[mi][1] = As[(rb0 + 8 + gid) * 36 + kb + tg];
                a[mi][2] = As[(rb0 + gid) * 36 + kb + 4 + tg];
                a[mi][3] = As[(rb0 + 8 + gid) * 36 + kb + 4 + tg];
            }
#pragma unroll
            for (int ni = 0; ni < 4; ++ni) {
                int col = wn * 32 + ni * 8 + gid;
                float b0 = Bs[(kb + tg) * 72 + col];
                float b1 = Bs[(kb + 4 + tg) * 72 + col];
#pragma unroll
                for (int mi = 0; mi < 2; ++mi) mma8(acc[mi][ni], a[mi], b0, b1);
            }
        }
        __syncthreads();
    }

#pragma unroll
    for (int mi = 0; mi < 2; ++mi)
#pragma unroll
        for (int half = 0; half < 2; ++half) {
            int row = m0 + wm * 32 + mi * 16 + half * 8 + gid;
#pragma unroll
            for (int ni = 0; ni < 4; ++ni)
#pragma unroll
                for (int e = 0; e < 2; ++e) {
                    int n = n0 + wn * 32 + ni * 8 + tg * 2 + e;
                    out[(size_t)row * VOCAB + n] = acc[mi][ni][half * 2 + e] + bo[n];
                }
        }
}

__global__ void gru_copy_hfinal(float* __restrict__ dst) {
    int i = blockIdx.x * blockDim.x + threadIdx.x;
    if (i < BATCH * HID) dst[i] = g_H[(size_t)SEQ * (BATCH * HID) + i];
}

// ---------------------------------------------------------------------------
extern "C" void kernel_launch(void* const* d_in, const int* in_sizes, int n_in,
                              void* d_out, int out_size)
{
    const int*   X  = (const int*)  d_in[0];
    const float* Wz = (const float*)d_in[1];
    const float* bz = (const float*)d_in[2];
    const float* Wr = (const float*)d_in[3];
    const float* br = (const float*)d_in[4];
    const float* Wh = (const float*)d_in[5];
    const float* bh = (const float*)d_in[6];
    const float* Wo = (const float*)d_in[7];
    const float* bo = (const float*)d_in[8];
    float* out = (float*)d_out;

    const int smemFloats = 16384 + 8192 + NSTG * 64 * SAPAD + 2 * 64 * RSTR + 512 + 512 + 64;
    const int smemBytes  = smemFloats * 4;   // 222464 B
    cudaFuncSetAttribute(gru_persist, cudaFuncAttributeMaxDynamicSharedMemorySize, smemBytes);

    gru_persist<<<NBLK, NTHR, smemBytes>>>(X, Wz, bz, Wr, br, Wh, bh);

    gru_out2<<<dim3(VOCAB / 64, (SEQ * BATCH) / 128), 256>>>(Wo, bo, out);

    const long long ybytes = (long long)SEQ * BATCH * VOCAB;
    if ((long long)out_size >= ybytes + (long long)BATCH * HID) {
        gru_copy_hfinal<<<64, 1024>>>(out + ybytes);
    }
    (void)in_sizes; (void)n_in;
}

// round 13
// speedup vs baseline: 1.3480x; 1.0289x over previous
#include <cuda_runtime.h>
#include <cstdint>

#define BATCH  64
#define HID    1024
#define VOCAB  4096
#define SEQ    256
#define NBLK   128
#define NTHR   512
#define CH     128                 // A-chunk width (cols of K)
#define NCH    (HID / CH)          // 8 chunks
#define SAPAD  132                 // padded row stride for sA
#define NSTG   3                   // cp.async pipeline stages
#define RSTR   36                  // sRed row stride (8 cols * 4 kq + 4 pad)

// ---------------------------------------------------------------------------
// Global scratch
// ---------------------------------------------------------------------------
__device__ float g_H[(SEQ + 1) * BATCH * HID];
__device__ float g_P[BATCH * HID];
__device__ unsigned g_bar_count = 0;
__device__ unsigned g_bar_gen   = 0;

// ---------------------------------------------------------------------------
// helpers
// ---------------------------------------------------------------------------
__device__ __forceinline__ float tf32r(float x) {
    unsigned u;
    asm("cvt.rna.tf32.f32 %0, %1;" : "=r"(u) : "f"(x));
    return __uint_as_float(u);
}

__device__ __forceinline__ void mma8(float (&c)[4], const float (&a)[4], float b0, float b1) {
    unsigned a0 = __float_as_uint(a[0]), a1 = __float_as_uint(a[1]);
    unsigned a2 = __float_as_uint(a[2]), a3 = __float_as_uint(a[3]);
    unsigned B0 = __float_as_uint(b0),  B1 = __float_as_uint(b1);
    asm volatile(
        "mma.sync.aligned.m16n8k8.row.col.f32.tf32.tf32.f32 "
        "{%0,%1,%2,%3}, {%4,%5,%6,%7}, {%8,%9}, {%0,%1,%2,%3};\n"
        : "+f"(c[0]), "+f"(c[1]), "+f"(c[2]), "+f"(c[3])
        : "r"(a0), "r"(a1), "r"(a2), "r"(a3), "r"(B0), "r"(B1));
}

__device__ __forceinline__ float sigmoidf_(float x) { return 1.f / (1.f + __expf(-x)); }

__device__ __forceinline__ void cpasync16(uint32_t daddr, const float* gptr) {
    asm volatile("cp.async.cg.shared.global [%0], [%1], 16;\n"
                 :: "r"(daddr), "l"(gptr) : "memory");
}
__device__ __forceinline__ void cpasync_commit() {
    asm volatile("cp.async.commit_group;\n" ::: "memory");
}
template<int N>
__device__ __forceinline__ void cpasync_wait() {
    asm volatile("cp.async.wait_group %0;\n" :: "n"(N) : "memory");
}

// Light release/acquire grid barrier (thread 0 only touches global).
__device__ __forceinline__ void gridbar() {
    __syncthreads();
    if (threadIdx.x == 0) {
        unsigned gen;
        asm volatile("ld.relaxed.gpu.global.u32 %0, [%1];"
                     : "=r"(gen) : "l"(&g_bar_gen) : "memory");
        unsigned old;
        asm volatile("atom.acq_rel.gpu.global.add.u32 %0, [%1], 1;"
                     : "=r"(old) : "l"(&g_bar_count) : "memory");
        if (old == NBLK - 1) {
            asm volatile("st.relaxed.gpu.global.u32 [%0], %1;"
                         :: "l"(&g_bar_count), "r"(0u) : "memory");
            asm volatile("st.release.gpu.global.u32 [%0], %1;"
                         :: "l"(&g_bar_gen), "r"(gen + 1) : "memory");
        } else {
            unsigned cur;
            do {
                asm volatile("ld.acquire.gpu.global.u32 %0, [%1];"
                             : "=r"(cur) : "l"(&g_bar_gen) : "memory");
            } while (cur == gen);
        }
    }
    __syncthreads();
}

// ---------------------------------------------------------------------------
// Persistent recurrence: 128 blocks x 512 threads; block b owns cols
// [8b, 8b+8) of ALL THREE gates. Single-sync 3-stage cp.async ring:
//   iter it: wait(chunk it) -> sync -> refill chunk it+2 into stage (it+2)%3
//   (safe: that stage held chunk it-1, whose reads finished before this sync)
//   -> MMA chunk it.
// ---------------------------------------------------------------------------
__global__ void __launch_bounds__(NTHR, 1)
gru_persist(const int* __restrict__ X,
            const float* __restrict__ Wz, const float* __restrict__ bz,
            const float* __restrict__ Wr, const float* __restrict__ br,
            const float* __restrict__ Wh, const float* __restrict__ bh)
{
    extern __shared__ float sm[];
    float* sWa  = sm;                        // 16384 : z|r weights (float4 frag)
    float* sWh  = sWa + 16384;               //  8192 : h weights (float2 frag)
    float* sA   = sWh + 8192;                // 25344 : A ring [3][64][SAPAD]
    float* sRed = sA + NSTG * 64 * SAPAD;    //  4608 : partials [gate][row][col][kq]
    float* sZ   = sRed + 2 * 64 * RSTR;      //   512 : z gate [64][8]
    float* sHc  = sZ + 512;                  //   512 : own-col H(t) [64][8]

    const int tid  = threadIdx.x;
    const int bid  = blockIdx.x;
    const int lane = tid & 31;
    const int wid  = tid >> 5;
    const int mt   = wid >> 2;
    const int kq   = wid & 3;
    const int gid  = lane >> 2;
    const int tg   = lane & 3;
    const int n0   = bid * 8;
    const int g0   = bid >> 4;               // chunk containing own columns
    const int lcol = 8 * (bid & 15);         // own-col offset inside chunk g0

    // epilogue thread mapping (all 512 threads)
    const int erow = tid >> 3;
    const int ecol = tid & 7;
    const int en   = n0 + ecol;

    // copy coords
    const int crow = tid >> 5;
    const int ckw  = tid & 31;
    uint32_t sbase = (uint32_t)__cvta_generic_to_shared(sA);

    // ---- pack weights once: phase A float4 {z.b0,z.b1,r.b0,r.b1} ----
    for (int e = tid; e < 16384; e += NTHR) {
        int c = e & 3, ln = (e >> 2) & 31, k8 = e >> 7;
        int k   = k8 * 8 + (c & 1) * 4 + (ln & 3);
        int col = n0 + (ln >> 2);
        const float* W = (c >> 1) ? Wr : Wz;
        sWa[e] = tf32r(W[(size_t)(VOCAB + k) * HID + col]);
    }
    for (int e = tid; e < 8192; e += NTHR) {
        int reg = e & 1, ln = (e >> 1) & 31, k8 = e >> 6;
        int k   = k8 * 8 + reg * 4 + (ln & 3);
        int col = n0 + (ln >> 2);
        sWh[e] = tf32r(Wh[(size_t)(VOCAB + k) * HID + col]);
    }

    // bias preload (thread-fixed columns)
    const float bzv = bz[en], brv = br[en], bhv = bh[en];

    // zero H0
    g_H[bid * NTHR + tid] = 0.f;
    gridbar();

    for (int t = 0; t < SEQ; ++t) {
        const float* Hc = g_H + (size_t)t * (BATCH * HID);
        float*       Hn = g_H + (size_t)(t + 1) * (BATCH * HID);

        // prefetch gather operands for both epilogues (consumed chunks later)
        const int x = __ldg(X + erow * SEQ + t);
        const size_t wix = (size_t)x * HID + en;
        const float wzv = __ldg(Wz + wix);
        const float wrv = __ldg(Wr + wix);
        const float whv = __ldg(Wh + wix);

        // ================= Phase A: z and r =================
        {
            float az[4] = {0,0,0,0}, ar[4] = {0,0,0,0};

            // prologue: chunks 0..2 -> stages 0..2
#pragma unroll
            for (int c = 0; c < NSTG; ++c) {
#pragma unroll
                for (int j = 0; j < 4; ++j) {
                    int row = j * 16 + crow;
                    uint32_t d = sbase + (c * (64 * SAPAD) + row * SAPAD + ckw * 4) * 4;
                    cpasync16(d, Hc + (size_t)row * HID + c * CH + ckw * 4);
                }
                cpasync_commit();
            }

#pragma unroll
            for (int it = 0; it < NCH; ++it) {
                if (it == 0)           cpasync_wait<2>();
                else if (it + 1 < NCH) cpasync_wait<1>();
                else                   cpasync_wait<0>();
                __syncthreads();

                // refill chunk it+2 into stage (it+2)%3 (== stage of chunk it-1)
                if (it >= 1 && it + 2 < NCH) {
                    int c = it + 2;
#pragma unroll
                    for (int j = 0; j < 4; ++j) {
                        int row = j * 16 + crow;
                        uint32_t d = sbase + ((c % NSTG) * (64 * SAPAD) + row * SAPAD + ckw * 4) * 4;
                        cpasync16(d, Hc + (size_t)row * HID + c * CH + ckw * 4);
                    }
                    cpasync_commit();
                }

                const float* stg = sA + (it % NSTG) * (64 * SAPAD);
                if (it == g0) sHc[tid] = stg[erow * SAPAD + lcol + ecol];

                const float* aBase = stg + (mt * 16 + gid) * SAPAD;
#pragma unroll
                for (int i = 0; i < 4; ++i) {
                    int k8l = kq * 4 + i;
                    int kb  = k8l * 8;
                    float a[4];
                    a[0] = tf32r(aBase[kb + tg]);
                    a[1] = tf32r(aBase[8 * SAPAD + kb + tg]);
                    a[2] = tf32r(aBase[kb + 4 + tg]);
                    a[3] = tf32r(aBase[8 * SAPAD + kb + 4 + tg]);
                    int k8g = it * 16 + k8l;
                    float4 w = *reinterpret_cast<const float4*>(sWa + (k8g * 32 + lane) * 4);
                    mma8(az, a, w.x, w.y);
                    mma8(ar, a, w.z, w.w);
                }
            }

            // partials: all warps -> sRed[gate][row][col][kq]
#pragma unroll
            for (int j = 0; j < 4; ++j) {
                int prow = mt * 16 + gid + (j >> 1) * 8;
                int pcol = tg * 2 + (j & 1);
                sRed[prow * RSTR + pcol * 4 + kq]             = az[j];
                sRed[64 * RSTR + prow * RSTR + pcol * 4 + kq] = ar[j];
            }
            __syncthreads();

            // wide epilogue: one (row,col) per thread
            {
                float4 zp = *reinterpret_cast<const float4*>(sRed + erow * RSTR + ecol * 4);
                float4 rp = *reinterpret_cast<const float4*>(sRed + 64 * RSTR + erow * RSTR + ecol * 4);
                float zsum = ((zp.x + zp.y) + zp.z) + zp.w;
                float rsum = ((rp.x + rp.y) + rp.z) + rp.w;
                float zv = sigmoidf_(zsum + wzv + bzv);
                float rv = sigmoidf_(rsum + wrv + brv);
                sZ[tid] = zv;
                __stcg(g_P + erow * HID + en, rv * sHc[tid]);
            }
        }
        gridbar();

        // ================= Phase B: h gate + H update =================
        {
            float ah[4] = {0,0,0,0};

#pragma unroll
            for (int c = 0; c < NSTG; ++c) {
#pragma unroll
                for (int j = 0; j < 4; ++j) {
                    int row = j * 16 + crow;
                    uint32_t d = sbase + (c * (64 * SAPAD) + row * SAPAD + ckw * 4) * 4;
                    cpasync16(d, g_P + (size_t)row * HID + c * CH + ckw * 4);
                }
                cpasync_commit();
            }

#pragma unroll
            for (int it = 0; it < NCH; ++it) {
                if (it == 0)           cpasync_wait<2>();
                else if (it + 1 < NCH) cpasync_wait<1>();
                else                   cpasync_wait<0>();
                __syncthreads();

                if (it >= 1 && it + 2 < NCH) {
                    int c = it + 2;
#pragma unroll
                    for (int j = 0; j < 4; ++j) {
                        int row = j * 16 + crow;
                        uint32_t d = sbase + ((c % NSTG) * (64 * SAPAD) + row * SAPAD + ckw * 4) * 4;
                        cpasync16(d, g_P + (size_t)row * HID + c * CH + ckw * 4);
                    }
                    cpasync_commit();
                }

                const float* aBase = sA + (it % NSTG) * (64 * SAPAD) + (mt * 16 + gid) * SAPAD;
#pragma unroll
                for (int i = 0; i < 4; ++i) {
                    int k8l = kq * 4 + i;
                    int kb  = k8l * 8;
                    float a[4];
                    a[0] = tf32r(aBase[kb + tg]);
                    a[1] = tf32r(aBase[8 * SAPAD + kb + tg]);
                    a[2] = tf32r(aBase[kb + 4 + tg]);
                    a[3] = tf32r(aBase[8 * SAPAD + kb + 4 + tg]);
                    int k8g = it * 16 + k8l;
                    float2 b = *reinterpret_cast<const float2*>(sWh + (k8g * 32 + lane) * 2);
                    mma8(ah, a, b.x, b.y);
                }
            }

#pragma unroll
            for (int j = 0; j < 4; ++j) {
                int prow = mt * 16 + gid + (j >> 1) * 8;
                int pcol = tg * 2 + (j & 1);
                sRed[prow * RSTR + pcol * 4 + kq] = ah[j];
            }
            __syncthreads();

            {
                float4 hp = *reinterpret_cast<const float4*>(sRed + erow * RSTR + ecol * 4);
                float hsum = ((hp.x + hp.y) + hp.z) + hp.w;
                float hv = tanhf(hsum + whv + bhv);
                float zv = sZ[tid];
                float hc = sHc[tid];
                __stcg(Hn + erow * HID + en, zv * hv + (1.f - zv) * hc);
            }
        }
        gridbar();
    }
}

// ---------------------------------------------------------------------------
// Output GEMM: Y = H_all[16384 x 1024] @ Wo[1024 x 4096] + bo
//   128x128 block tile, 512 threads (16 warps: 4 m x 4 n). Same K order as
//   before -> bit-identical results, ~2/3 the L2 traffic.
// ---------------------------------------------------------------------------
__global__ void __launch_bounds__(512)
gru_out3(const float* __restrict__ Wo, const float* __restrict__ bo,
         float* __restrict__ out)
{
    __shared__ float As[128 * 36];
    __shared__ float Bs[32 * 136];

    const int n0 = blockIdx.x * 128;
    const int m0 = blockIdx.y * 128;
    const float* A = g_H + (size_t)(BATCH * HID) + (size_t)m0 * HID;

    const int tid = threadIdx.x, lane = tid & 31, w = tid >> 5;
    const int wm = w >> 2, wn = w & 3, gid = lane >> 2, tg = lane & 3;

    float acc[2][4][4];
#pragma unroll
    for (int mi = 0; mi < 2; ++mi)
#pragma unroll
        for (int ni = 0; ni < 4; ++ni)
#pragma unroll
            for (int e = 0; e < 4; ++e) acc[mi][ni][e] = 0.f;

    float4 ra[2]; float4 rb[2];
#pragma unroll
    for (int j = 0; j < 2; ++j) {
        int i = tid + j * 512, row = i >> 3, kq8 = i & 7;
        ra[j] = *reinterpret_cast<const float4*>(A + (size_t)row * HID + kq8 * 4);
    }
#pragma unroll
    for (int j = 0; j < 2; ++j) {
        int i = tid + j * 512, row = i >> 5, nq = i & 31;
        rb[j] = *reinterpret_cast<const float4*>(Wo + (size_t)row * VOCAB + n0 + nq * 4);
    }

    for (int kk = 0; kk < HID; kk += 32) {
#pragma unroll
        for (int j = 0; j < 2; ++j) {
            int i = tid + j * 512, row = i >> 3, kq8 = i & 7;
            float4 v; v.x = tf32r(ra[j].x); v.y = tf32r(ra[j].y);
            v.z = tf32r(ra[j].z); v.w = tf32r(ra[j].w);
            *reinterpret_cast<float4*>(As + row * 36 + kq8 * 4) = v;
        }
#pragma unroll
        for (int j = 0; j < 2; ++j) {
            int i = tid + j * 512, row = i >> 5, nq = i & 31;
            float4 v; v.x = tf32r(rb[j].x); v.y = tf32r(rb[j].y);
            v.z = tf32r(rb[j].z); v.w = tf32r(rb[j].w);
            *reinterpret_cast<float4*>(Bs + row * 136 + nq * 4) = v;
        }
        __syncthreads();
        if (kk + 32 < HID) {
#pragma unroll
            for (int j = 0; j < 2; ++j) {
                int i = tid + j * 512, row = i >> 3, kq8 = i & 7;
                ra[j] = *reinterpret_cast<const float4*>(A + (size_t)row * HID + kk + 32 + kq8 * 4);
            }
#pragma unroll
            for (int j = 0; j < 2; ++j) {
                int i = tid + j * 512, row = i >> 5, nq = i & 31;
                rb[j] = *reinterpret_cast<const float4*>(
                    Wo + (size_t)(kk + 32 + row) * VOCAB + n0 + nq * 4);
            }
        }
#pragma unroll
        for (int k8 = 0; k8 < 4; ++k8) {
            int kb = k8 * 8;
            float a[2][4];
#pragma unroll
            for (int mi = 0; mi < 2; ++mi) {
                int rb0 = wm * 32 + mi * 16;
                a[mi][0] = As[(rb0 + gid) * 36 + kb + tg];
                a[mi][1] = As[(rb0 + 8 + gid) * 36 + kb + tg];
                a[mi][2] = As[(rb0 + gid) * 36 + kb + 4 + tg];
                a[mi][3] = As[(rb0 + 8 + gid) * 36 + kb + 4 + tg];
            }
#pragma unroll
            for (int ni = 0; ni < 4; ++ni) {
                int col = wn * 32 + ni * 8 + gid;
                float b0 = Bs[(kb + tg) * 136 + col];
                float b1 = Bs[(kb + 4 + tg) * 136 + col];
#pragma unroll
                for (int mi = 0; mi < 2; ++mi) mma8(acc[mi][ni], a[mi], b0, b1);
            }
        }
        __syncthreads();
    }

#pragma unroll
    for (int mi = 0; mi < 2; ++mi)
#pragma unroll
        for (int half = 0; half < 2; ++half) {
            int row = m0 + wm * 32 + mi * 16 + half * 8 + gid;
#pragma unroll
            for (int ni = 0; ni < 4; ++ni)
#pragma unroll
                for (int e = 0; e < 2; ++e) {
                    int n = n0 + wn * 32 + ni * 8 + tg * 2 + e;
                    out[(size_t)row * VOCAB + n] = acc[mi][ni][half * 2 + e] + bo[n];
                }
        }
}

__global__ void gru_copy_hfinal(float* __restrict__ dst) {
    int i = blockIdx.x * blockDim.x + threadIdx.x;
    if (i < BATCH * HID) dst[i] = g_H[(size_t)SEQ * (BATCH * HID) + i];
}

// ---------------------------------------------------------------------------
extern "C" void kernel_launch(void* const* d_in, const int* in_sizes, int n_in,
                              void* d_out, int out_size)
{
    const int*   X  = (const int*)  d_in[0];
    const float* Wz = (const float*)d_in[1];
    const float* bz = (const float*)d_in[2];
    const float* Wr = (const float*)d_in[3];
    const float* br = (const float*)d_in[4];
    const float* Wh = (const float*)d_in[5];
    const float* bh = (const float*)d_in[6];
    const float* Wo = (const float*)d_in[7];
    const float* bo = (const float*)d_in[8];
    float* out = (float*)d_out;

    const int smemFloats = 16384 + 8192 + NSTG * 64 * SAPAD + 2 * 64 * RSTR + 512 + 512;
    const int smemBytes  = smemFloats * 4;   // 222208 B
    cudaFuncSetAttribute(gru_persist, cudaFuncAttributeMaxDynamicSharedMemorySize, smemBytes);

    gru_persist<<<NBLK, NTHR, smemBytes>>>(X, Wz, bz, Wr, br, Wh, bh);

    gru_out3<<<dim3(VOCAB / 128, (SEQ * BATCH) / 128), 512>>>(Wo, bo, out);

    const long long ybytes = (long long)SEQ * BATCH * VOCAB;
    if ((long long)out_size >= ybytes + (long long)BATCH * HID) {
        gru_copy_hfinal<<<64, 1024>>>(out + ybytes);
    }
    (void)in_sizes; (void)n_in;
}

// round 14
// speedup vs baseline: 1.6842x; 1.2494x over previous
#include <cuda_runtime.h>
#include <cuda_fp16.h>
#include <cstdint>

#define BATCH  64
#define HID    1024
#define VOCAB  4096
#define SEQ    256
#define NBLK   128
#define NTHR   512
#define CH     256                 // A-chunk width (K cols), fp16
#define NCH    (HID / CH)          // 4 chunks
#define CHP    264                 // padded row stride (halves): 264*2B/4=132 words, %32=4
#define NSTG   3                   // cp.async pipeline stages
#define RSTR   36                  // sRed row stride (8 cols * 4 kq + 4 pad)

// ---------------------------------------------------------------------------
// Global scratch
// ---------------------------------------------------------------------------
__device__ float  g_H[(SEQ + 1) * BATCH * HID];   // fp32 history (output GEMM)
__device__ __half g_Hh[BATCH * HID];              // fp16 current H (GEMM operand)
__device__ __half g_Ph[BATCH * HID];              // fp16 P = r*H (GEMM operand)
__device__ unsigned g_bar_count = 0;
__device__ unsigned g_bar_gen   = 0;

// ---------------------------------------------------------------------------
// helpers
// ---------------------------------------------------------------------------
__device__ __forceinline__ float tf32r(float x) {
    unsigned u;
    asm("cvt.rna.tf32.f32 %0, %1;" : "=r"(u) : "f"(x));
    return __uint_as_float(u);
}

// tf32 m16n8k8 (output GEMM only)
__device__ __forceinline__ void mma8(float (&c)[4], const float (&a)[4], float b0, float b1) {
    unsigned a0 = __float_as_uint(a[0]), a1 = __float_as_uint(a[1]);
    unsigned a2 = __float_as_uint(a[2]), a3 = __float_as_uint(a[3]);
    unsigned B0 = __float_as_uint(b0),  B1 = __float_as_uint(b1);
    asm volatile(
        "mma.sync.aligned.m16n8k8.row.col.f32.tf32.tf32.f32 "
        "{%0,%1,%2,%3}, {%4,%5,%6,%7}, {%8,%9}, {%0,%1,%2,%3};\n"
        : "+f"(c[0]), "+f"(c[1]), "+f"(c[2]), "+f"(c[3])
        : "r"(a0), "r"(a1), "r"(a2), "r"(a3), "r"(B0), "r"(B1));
}

// fp16 m16n8k16, fp32 accumulate (recurrence GEMMs)
__device__ __forceinline__ void mma16(float (&c)[4],
                                      unsigned a0, unsigned a1, unsigned a2, unsigned a3,
                                      unsigned b0, unsigned b1) {
    asm volatile(
        "mma.sync.aligned.m16n8k16.row.col.f32.f16.f16.f32 "
        "{%0,%1,%2,%3}, {%4,%5,%6,%7}, {%8,%9}, {%0,%1,%2,%3};\n"
        : "+f"(c[0]), "+f"(c[1]), "+f"(c[2]), "+f"(c[3])
        : "r"(a0), "r"(a1), "r"(a2), "r"(a3), "r"(b0), "r"(b1));
}

__device__ __forceinline__ float sigmoidf_(float x) { return 1.f / (1.f + __expf(-x)); }

__device__ __forceinline__ unsigned packh2(float lo, float hi) {
    __half2 h = __floats2half2_rn(lo, hi);
    return *reinterpret_cast<unsigned*>(&h);
}

__device__ __forceinline__ void cpasync16(uint32_t daddr, const void* gptr) {
    asm volatile("cp.async.cg.shared.global [%0], [%1], 16;\n"
                 :: "r"(daddr), "l"(gptr) : "memory");
}
__device__ __forceinline__ void cpasync_commit() {
    asm volatile("cp.async.commit_group;\n" ::: "memory");
}
template<int N>
__device__ __forceinline__ void cpasync_wait() {
    asm volatile("cp.async.wait_group %0;\n" :: "n"(N) : "memory");
}

// Light release/acquire grid barrier (thread 0 only touches global).
__device__ __forceinline__ void gridbar() {
    __syncthreads();
    if (threadIdx.x == 0) {
        unsigned gen;
        asm volatile("ld.relaxed.gpu.global.u32 %0, [%1];"
                     : "=r"(gen) : "l"(&g_bar_gen) : "memory");
        unsigned old;
        asm volatile("atom.acq_rel.gpu.global.add.u32 %0, [%1], 1;"
                     : "=r"(old) : "l"(&g_bar_count) : "memory");
        if (old == NBLK - 1) {
            asm volatile("st.relaxed.gpu.global.u32 [%0], %1;"
                         :: "l"(&g_bar_count), "r"(0u) : "memory");
            asm volatile("st.release.gpu.global.u32 [%0], %1;"
                         :: "l"(&g_bar_gen), "r"(gen + 1) : "memory");
        } else {
            unsigned cur;
            do {
                asm volatile("ld.acquire.gpu.global.u32 %0, [%1];"
                             : "=r"(cur) : "l"(&g_bar_gen) : "memory");
            } while (cur == gen);
        }
    }
    __syncthreads();
}

// ---------------------------------------------------------------------------
// Persistent recurrence: 128 blocks x 512 threads; block b owns cols
// [8b, 8b+8) of ALL THREE gates. fp16 m16n8k16 GEMMs, fp32 state.
//   Single-sync 3-stage cp.async ring over NCH=4 chunks of 256 K.
// ---------------------------------------------------------------------------
__global__ void __launch_bounds__(NTHR, 1)
gru_persist(const int* __restrict__ X,
            const float* __restrict__ Wz, const float* __restrict__ bz,
            const float* __restrict__ Wr, const float* __restrict__ br,
            const float* __restrict__ Wh, const float* __restrict__ bh)
{
    extern __shared__ unsigned char smraw[];
    uint32_t* sWa32 = reinterpret_cast<uint32_t*>(smraw);        // 8192 u32 (32KB): z|r frags
    uint32_t* sWh32 = sWa32 + 8192;                              // 4096 u32 (16KB): h frags
    __half*   sAh   = reinterpret_cast<__half*>(sWh32 + 4096);   // 3*64*CHP halves (~99KB)
    float*    sRed  = reinterpret_cast<float*>(sAh + NSTG * 64 * CHP);  // 4608 f
    float*    sZ    = sRed + 2 * 64 * RSTR;                      // 512 f
    float*    sHc   = sZ + 512;                                  // 512 f (own-col H, fp32)

    const int tid  = threadIdx.x;
    const int bid  = blockIdx.x;
    const int lane = tid & 31;
    const int wid  = tid >> 5;
    const int mt   = wid >> 2;
    const int kq   = wid & 3;
    const int gid  = lane >> 2;
    const int tg   = lane & 3;
    const int n0   = bid * 8;

    // epilogue thread mapping
    const int erow = tid >> 3;
    const int ecol = tid & 7;
    const int en   = n0 + ecol;

    uint32_t sbase = (uint32_t)__cvta_generic_to_shared(sAh);

    // ---- pack weights once (fp16 b-fragments, RNE) ----
    // sWa32[e]: e = (k16*32 + lane)*4 + c, c = {z_b0, z_b1, r_b0, r_b1}
    for (int e = tid; e < 8192; e += NTHR) {
        int c = e & 3, ln = (e >> 2) & 31, k16 = e >> 7;
        int tgp = ln & 3, gidp = ln >> 2;
        int kb  = k16 * 16 + (c & 1) * 8 + 2 * tgp;
        const float* W = (c >> 1) ? Wr : Wz;
        int col = n0 + gidp;
        sWa32[e] = packh2(W[(size_t)(VOCAB + kb) * HID + col],
                          W[(size_t)(VOCAB + kb + 1) * HID + col]);
    }
    for (int e = tid; e < 4096; e += NTHR) {
        int c = e & 1, ln = (e >> 1) & 31, k16 = e >> 6;
        int tgp = ln & 3, gidp = ln >> 2;
        int kb  = k16 * 16 + c * 8 + 2 * tgp;
        int col = n0 + gidp;
        sWh32[e] = packh2(Wh[(size_t)(VOCAB + kb) * HID + col],
                          Wh[(size_t)(VOCAB + kb + 1) * HID + col]);
    }

    // bias preload
    const float bzv = bz[en], brv = br[en], bhv = bh[en];

    // init: H0 = 0 (fp16 operand buffer + own-col fp32 state)
    {
        int idx = bid * NTHR + tid;                 // 65536 = 64*1024
        reinterpret_cast<unsigned short*>(g_Hh)[idx] = 0;
        sHc[tid] = 0.f;
    }
    gridbar();

    for (int t = 0; t < SEQ; ++t) {
        float* Hn = g_H + (size_t)(t + 1) * (BATCH * HID);

        // prefetch gather operands for both epilogues
        const int x = __ldg(X + erow * SEQ + t);
        const size_t wix = (size_t)x * HID + en;
        const float wzv = __ldg(Wz + wix);
        const float wrv = __ldg(Wr + wix);
        const float whv = __ldg(Wh + wix);

        // ================= Phase A: z and r =================
        {
            float az[4] = {0,0,0,0}, ar[4] = {0,0,0,0};

            // prologue: chunks 0..2 -> stages 0..2
#pragma unroll
            for (int c = 0; c < NSTG; ++c) {
#pragma unroll
                for (int j = 0; j < 4; ++j) {
                    int seg = j * NTHR + tid;            // 2048 segs of 16B
                    int row = seg >> 5, s = seg & 31;
                    uint32_t d = sbase + (c * (64 * CHP) + row * CHP + s * 8) * 2;
                    cpasync16(d, g_Hh + (size_t)row * HID + c * CH + s * 8);
                }
                cpasync_commit();
            }

#pragma unroll
            for (int it = 0; it < NCH; ++it) {
                if (it == 0)           cpasync_wait<NSTG - 1>();
                else if (it + 1 < NCH) cpasync_wait<1>();
                else                   cpasync_wait<0>();
                __syncthreads();

                // refill chunk it+2 into stage (it+2)%3 (held chunk it-1)
                if (it >= 1 && it + 2 < NCH) {
                    int c = it + 2;
#pragma unroll
                    for (int j = 0; j < 4; ++j) {
                        int seg = j * NTHR + tid;
                        int row = seg >> 5, s = seg & 31;
                        uint32_t d = sbase + ((c % NSTG) * (64 * CHP) + row * CHP + s * 8) * 2;
                        cpasync16(d, g_Hh + (size_t)row * HID + c * CH + s * 8);
                    }
                    cpasync_commit();
                }

                const __half* stg = sAh + (it % NSTG) * (64 * CHP);
                const int row0 = mt * 16 + gid;
#pragma unroll
                for (int i = 0; i < 4; ++i) {
                    int k16l = kq * 4 + i;
                    int kk   = k16l * 16;
                    unsigned u0 = *reinterpret_cast<const unsigned*>(stg + row0 * CHP + kk + 2 * tg);
                    unsigned u1 = *reinterpret_cast<const unsigned*>(stg + (row0 + 8) * CHP + kk + 2 * tg);
                    unsigned u2 = *reinterpret_cast<const unsigned*>(stg + row0 * CHP + kk + 8 + 2 * tg);
                    unsigned u3 = *reinterpret_cast<const unsigned*>(stg + (row0 + 8) * CHP + kk + 8 + 2 * tg);
                    int k16g = it * 16 + k16l;
                    uint4 w = *reinterpret_cast<const uint4*>(sWa32 + (size_t)(k16g * 32 + lane) * 4);
                    mma16(az, u0, u1, u2, u3, w.x, w.y);
                    mma16(ar, u0, u1, u2, u3, w.z, w.w);
                }
            }

            // partials -> sRed[gate][row][col][kq]
#pragma unroll
            for (int j = 0; j < 4; ++j) {
                int prow = mt * 16 + gid + (j >> 1) * 8;
                int pcol = tg * 2 + (j & 1);
                sRed[prow * RSTR + pcol * 4 + kq]             = az[j];
                sRed[64 * RSTR + prow * RSTR + pcol * 4 + kq] = ar[j];
            }
            __syncthreads();

            // wide epilogue: one (row,col) per thread
            {
                float4 zp = *reinterpret_cast<const float4*>(sRed + erow * RSTR + ecol * 4);
                float4 rp = *reinterpret_cast<const float4*>(sRed + 64 * RSTR + erow * RSTR + ecol * 4);
                float zsum = ((zp.x + zp.y) + zp.z) + zp.w;
                float rsum = ((rp.x + rp.y) + rp.z) + rp.w;
                float zv = sigmoidf_(zsum + wzv + bzv);
                float rv = sigmoidf_(rsum + wrv + brv);
                sZ[tid] = zv;
                g_Ph[erow * HID + en] = __float2half_rn(rv * sHc[tid]);
            }
        }
        gridbar();

        // ================= Phase B: h gate + H update =================
        {
            float ah[4] = {0,0,0,0};

#pragma unroll
            for (int c = 0; c < NSTG; ++c) {
#pragma unroll
                for (int j = 0; j < 4; ++j) {
                    int seg = j * NTHR + tid;
                    int row = seg >> 5, s = seg & 31;
                    uint32_t d = sbase + (c * (64 * CHP) + row * CHP + s * 8) * 2;
                    cpasync16(d, g_Ph + (size_t)row * HID + c * CH + s * 8);
                }
                cpasync_commit();
            }

#pragma unroll
            for (int it = 0; it < NCH; ++it) {
                if (it == 0)           cpasync_wait<NSTG - 1>();
                else if (it + 1 < NCH) cpasync_wait<1>();
                else                   cpasync_wait<0>();
                __syncthreads();

                if (it >= 1 && it + 2 < NCH) {
                    int c = it + 2;
#pragma unroll
                    for (int j = 0; j < 4; ++j) {
                        int seg = j * NTHR + tid;
                        int row = seg >> 5, s = seg & 31;
                        uint32_t d = sbase + ((c % NSTG) * (64 * CHP) + row * CHP + s * 8) * 2;
                        cpasync16(d, g_Ph + (size_t)row * HID + c * CH + s * 8);
                    }
                    cpasync_commit();
                }

                const __half* stg = sAh + (it % NSTG) * (64 * CHP);
                const int row0 = mt * 16 + gid;
#pragma unroll
                for (int i = 0; i < 4; ++i) {
                    int k16l = kq * 4 + i;
                    int kk   = k16l * 16;
                    unsigned u0 = *reinterpret_cast<const unsigned*>(stg + row0 * CHP + kk + 2 * tg);
                    unsigned u1 = *reinterpret_cast<const unsigned*>(stg + (row0 + 8) * CHP + kk + 2 * tg);
                    unsigned u2 = *reinterpret_cast<const unsigned*>(stg + row0 * CHP + kk + 8 + 2 * tg);
                    unsigned u3 = *reinterpret_cast<const unsigned*>(stg + (row0 + 8) * CHP + kk + 8 + 2 * tg);
                    int k16g = it * 16 + k16l;
                    uint2 w = *reinterpret_cast<const uint2*>(sWh32 + (size_t)(k16g * 32 + lane) * 2);
                    mma16(ah, u0, u1, u2, u3, w.x, w.y);
                }
            }

#pragma unroll
            for (int j = 0; j < 4; ++j) {
                int prow = mt * 16 + gid + (j >> 1) * 8;
                int pcol = tg * 2 + (j & 1);
                sRed[prow * RSTR + pcol * 4 + kq] = ah[j];
            }
            __syncthreads();

            {
                float4 hp = *reinterpret_cast<const float4*>(sRed + erow * RSTR + ecol * 4);
                float hsum = ((hp.x + hp.y) + hp.z) + hp.w;
                float hv = tanhf(hsum + whv + bhv);
                float zv = sZ[tid];
                float hcold = sHc[tid];
                float hnew = zv * hv + (1.f - zv) * hcold;
                sHc[tid] = hnew;
                Hn[erow * HID + en] = hnew;                       // fp32 history
                g_Hh[erow * HID + en] = __float2half_rn(hnew);    // fp16 operand
            }
        }
        gridbar();
    }
}

// ---------------------------------------------------------------------------
// Output GEMM: Y = H_all[16384 x 1024] @ Wo[1024 x 4096] + bo
//   128x128 block tile, 512 threads (known-good R13 version, tf32).
// ---------------------------------------------------------------------------
__global__ void __launch_bounds__(512)
gru_out3(const float* __restrict__ Wo, const float* __restrict__ bo,
         float* __restrict__ out)
{
    __shared__ float As[128 * 36];
    __shared__ float Bs[32 * 136];

    const int n0 = blockIdx.x * 128;
    const int m0 = blockIdx.y * 128;
    const float* A = g_H + (size_t)(BATCH * HID) + (size_t)m0 * HID;

    const int tid = threadIdx.x, lane = tid & 31, w = tid >> 5;
    const int wm = w >> 2, wn = w & 3, gid = lane >> 2, tg = lane & 3;

    float acc[2][4][4];
#pragma unroll
    for (int mi = 0; mi < 2; ++mi)
#pragma unroll
        for (int ni = 0; ni < 4; ++ni)
#pragma unroll
            for (int e = 0; e < 4; ++e) acc[mi][ni][e] = 0.f;

    float4 ra[2]; float4 rb[2];
#pragma unroll
    for (int j = 0; j < 2; ++j) {
        int i = tid + j * 512, row = i >> 3, kq8 = i & 7;
        ra[j] = *reinterpret_cast<const float4*>(A + (size_t)row * HID + kq8 * 4);
    }
#pragma unroll
    for (int j = 0; j < 2; ++j) {
        int i = tid + j * 512, row = i >> 5, nq = i & 31;
        rb[j] = *reinterpret_cast<const float4*>(Wo + (size_t)row * VOCAB + n0 + nq * 4);
    }

    for (int kk = 0; kk < HID; kk += 32) {
#pragma unroll
        for (int j = 0; j < 2; ++j) {
            int i = tid + j * 512, row = i >> 3, kq8 = i & 7;
            float4 v; v.x = tf32r(ra[j].x); v.y = tf32r(ra[j].y);
            v.z = tf32r(ra[j].z); v.w = tf32r(ra[j].w);
            *reinterpret_cast<float4*>(As + row * 36 + kq8 * 4) = v;
        }
#pragma unroll
        for (int j = 0; j < 2; ++j) {
            int i = tid + j * 512, row = i >> 5, nq = i & 31;
            float4 v; v.x = tf32r(rb[j].x); v.y = tf32r(rb[j].y);
            v.z = tf32r(rb[j].z); v.w = tf32r(rb[j].w);
            *reinterpret_cast<float4*>(Bs + row * 136 + nq * 4) = v;
        }
        __syncthreads();
        if (kk + 32 < HID) {
#pragma unroll
            for (int j = 0; j < 2; ++j) {
                int i = tid + j * 512, row = i >> 3, kq8 = i & 7;
                ra[j] = *reinterpret_cast<const float4*>(A + (size_t)row * HID + kk + 32 + kq8 * 4);
            }
#pragma unroll
            for (int j = 0; j < 2; ++j) {
                int i = tid + j * 512, row = i >> 5, nq = i & 31;
                rb[j] = *reinterpret_cast<const float4*>(
                    Wo + (size_t)(kk + 32 + row) * VOCAB + n0 + nq * 4);
            }
        }
#pragma unroll
        for (int k8 = 0; k8 < 4; ++k8) {
            int kb = k8 * 8;
            float a[2][4];
#pragma unroll
            for (int mi = 0; mi < 2; ++mi) {
                int rb0 = wm * 32 + mi * 16;
                a[mi][0] = As[(rb0 + gid) * 36 + kb + tg];
                a[mi][1] = As[(rb0 + 8 + gid) * 36 + kb + tg];
                a[mi][2] = As[(rb0 + gid) * 36 + kb + 4 + tg];
                a[mi][3] = As[(rb0 + 8 + gid) * 36 + kb + 4 + tg];
            }
#pragma unroll
            for (int ni = 0; ni < 4; ++ni) {
                int col = wn * 32 + ni * 8 + gid;
                float b0 = Bs[(kb + tg) * 136 + col];
                float b1 = Bs[(kb + 4 + tg) * 136 + col];
#pragma unroll
                for (int mi = 0; mi < 2; ++mi) mma8(acc[mi][ni], a[mi], b0, b1);
            }
        }
        __syncthreads();
    }

#pragma unroll
    for (int mi = 0; mi < 2; ++mi)
#pragma unroll
        for (int half = 0; half < 2; ++half) {
            int row = m0 + wm * 32 + mi * 16 + half * 8 + gid;
#pragma unroll
            for (int ni = 0; ni < 4; ++ni)
#pragma unroll
                for (int e = 0; e < 2; ++e) {
                    int n = n0 + wn * 32 + ni * 8 + tg * 2 + e;
                    out[(size_t)row * VOCAB + n] = acc[mi][ni][half * 2 + e] + bo[n];
                }
        }
}

__global__ void gru_copy_hfinal(float* __restrict__ dst) {
    int i = blockIdx.x * blockDim.x + threadIdx.x;
    if (i < BATCH * HID) dst[i] = g_H[(size_t)SEQ * (BATCH * HID) + i];
}

// ---------------------------------------------------------------------------
extern "C" void kernel_launch(void* const* d_in, const int* in_sizes, int n_in,
                              void* d_out, int out_size)
{
    const int*   X  = (const int*)  d_in[0];
    const float* Wz = (const float*)d_in[1];
    const float* bz = (const float*)d_in[2];
    const float* Wr = (const float*)d_in[3];
    const float* br = (const float*)d_in[4];
    const float* Wh = (const float*)d_in[5];
    const float* bh = (const float*)d_in[6];
    const float* Wo = (const float*)d_in[7];
    const float* bo = (const float*)d_in[8];
    float* out = (float*)d_out;

    const int smemBytes = 8192 * 4            // sWa32
                        + 4096 * 4            // sWh32
                        + NSTG * 64 * CHP * 2 // fp16 A ring
                        + 2 * 64 * RSTR * 4   // sRed
                        + 512 * 4             // sZ
                        + 512 * 4;            // sHc  => 173056 B
    cudaFuncSetAttribute(gru_persist, cudaFuncAttributeMaxDynamicSharedMemorySize, smemBytes);

    gru_persist<<<NBLK, NTHR, smemBytes>>>(X, Wz, bz, Wr, br, Wh, bh);

    gru_out3<<<dim3(VOCAB / 128, (SEQ * BATCH) / 128), 512>>>(Wo, bo, out);

    const long long ybytes = (long long)SEQ * BATCH * VOCAB;
    if ((long long)out_size >= ybytes + (long long)BATCH * HID) {
        gru_copy_hfinal<<<64, 1024>>>(out + ybytes);
    }
    (void)in_sizes; (void)n_in;
}